// round 9
// baseline (speedup 1.0000x reference)
#include <cuda_runtime.h>
#include <cuda_bf16.h>
#include <cstdint>

// Problem constants
#define Bv   4
#define Tv   2048
#define Dv   1024
#define NH   16
#define HDim 64
#define BT   (Bv * Tv)          // 8192
#define QKVN (3 * Dv)           // 3072
#define KG   (3 * Dv)           // 3072 gemm split-K (bf16 3-term, verified R3)

// ---------------------------------------------------------------------------
// Scratch (device globals; no allocation allowed)
// ---------------------------------------------------------------------------
__device__ float         g_qkv[BT * QKVN];            // fp32 qkv          96MB
__device__ float         g_attn[BT * Dv];             // fp32 attn out     32MB
__device__ __nv_bfloat16 g_A1[(size_t)BT * KG];       // x split           48MB
__device__ __nv_bfloat16 g_A2[(size_t)BT * KG];       // attn-out split    48MB
__device__ __nv_bfloat16 g_Bt1[(size_t)QKVN * KG];    // Wqkv^T            18MB
__device__ __nv_bfloat16 g_Bt2[(size_t)Dv * KG];      // Wout^T             6MB

// ---------------------------------------------------------------------------
// Helpers
// ---------------------------------------------------------------------------
__device__ __forceinline__ uint32_t smem_u32(const void* p) {
    uint32_t a;
    asm("{ .reg .u64 t; cvta.to.shared.u64 t, %1; cvt.u32.u64 %0, t; }" : "=r"(a) : "l"(p));
    return a;
}
__device__ __forceinline__ void cp_async16(uint32_t dst, const void* src) {
    asm volatile("cp.async.cg.shared.global [%0], [%1], 16;" :: "r"(dst), "l"(src));
}
__device__ __forceinline__ void cp_commit() {
    asm volatile("cp.async.commit_group;" ::: "memory");
}
template <int N>
__device__ __forceinline__ void cp_wait() {
    asm volatile("cp.async.wait_group %0;" :: "n"(N) : "memory");
}
__device__ __forceinline__ void ldm_x4(uint32_t* r, uint32_t addr) {
    asm volatile("ldmatrix.sync.aligned.m8n8.x4.shared.b16 {%0,%1,%2,%3}, [%4];"
                 : "=r"(r[0]), "=r"(r[1]), "=r"(r[2]), "=r"(r[3]) : "r"(addr));
}
__device__ __forceinline__ void ldm_x2(uint32_t* r, uint32_t addr) {
    asm volatile("ldmatrix.sync.aligned.m8n8.x2.shared.b16 {%0,%1}, [%2];"
                 : "=r"(r[0]), "=r"(r[1]) : "r"(addr));
}
__device__ __forceinline__ void mma_bf16(float* d, const uint32_t* a, const uint32_t* b) {
    asm volatile(
        "mma.sync.aligned.m16n8k16.row.col.f32.bf16.bf16.f32 "
        "{%0,%1,%2,%3}, {%4,%5,%6,%7}, {%8,%9}, {%0,%1,%2,%3};"
        : "+f"(d[0]), "+f"(d[1]), "+f"(d[2]), "+f"(d[3])
        : "r"(a[0]), "r"(a[1]), "r"(a[2]), "r"(a[3]), "r"(b[0]), "r"(b[1]));
}

// ---------------------------------------------------------------------------
// bf16 HMMA GEMM (verbatim R3 — VERIFIED): C = A[M,KG] @ Bt[N,KG]^T
// ---------------------------------------------------------------------------
#define BM 128
#define BN 128
#define BK 32
#define KPAD 40
#define GSTAGES 3
#define KITERS (KG / BK)        // 96
#define STAGE_ELEMS ((BM + BN) * KPAD)
#define GEMM_SMEM (GSTAGES * STAGE_ELEMS * 2)

__global__ void __launch_bounds__(256)
gemm_mma(const __nv_bfloat16* __restrict__ A, const __nv_bfloat16* __restrict__ Bt,
         float* __restrict__ C, int N)
{
    extern __shared__ __nv_bfloat16 smg[];
    const int tid  = threadIdx.x;
    const int lane = tid & 31;
    const int wid  = tid >> 5;
    const int wm   = (wid & 1) * 64;
    const int wn   = (wid >> 1) * 32;
    const int m0   = blockIdx.y * BM;
    const int n0   = blockIdx.x * BN;

    const uint32_t smb = smem_u32(smg);

    const int idxA0 = tid * 2;
    const int rowA0 = idxA0 >> 2, kcA0 = (idxA0 & 3) * 8;
    const int rowA1 = (idxA0 + 1) >> 2, kcA1 = ((idxA0 + 1) & 3) * 8;

    float acc[4][4][4] = {};

    #define ISSUE_STAGE(it, s) do { \
        const __nv_bfloat16* ga = A  + (size_t)m0 * KG + (it) * BK; \
        const __nv_bfloat16* gb = Bt + (size_t)n0 * KG + (it) * BK; \
        uint32_t sa = smb + (uint32_t)(s) * STAGE_ELEMS * 2; \
        uint32_t sb = sa + BM * KPAD * 2; \
        cp_async16(sa + (rowA0 * KPAD + kcA0) * 2, ga + (size_t)rowA0 * KG + kcA0); \
        cp_async16(sa + (rowA1 * KPAD + kcA1) * 2, ga + (size_t)rowA1 * KG + kcA1); \
        cp_async16(sb + (rowA0 * KPAD + kcA0) * 2, gb + (size_t)rowA0 * KG + kcA0); \
        cp_async16(sb + (rowA1 * KPAD + kcA1) * 2, gb + (size_t)rowA1 * KG + kcA1); \
    } while (0)

    #pragma unroll
    for (int s = 0; s < GSTAGES; ++s) { ISSUE_STAGE(s, s); cp_commit(); }

    const int aRowSel = wm + (lane & 15);
    const int aColSel = (lane >> 4) << 3;
    const int bRowSel = wn + (lane & 7);
    const int bColSel = ((lane >> 3) & 1) << 3;

    for (int it = 0; it < KITERS; ++it) {
        const int s = it % GSTAGES;
        cp_wait<GSTAGES - 1>();
        __syncthreads();

        const uint32_t sa = smb + (uint32_t)s * STAGE_ELEMS * 2;
        const uint32_t sb = sa + BM * KPAD * 2;

        #pragma unroll
        for (int ks = 0; ks < 2; ++ks) {
            const int k0 = ks * 16;
            uint32_t afr[4][4], bfr[4][2];
            #pragma unroll
            for (int mt = 0; mt < 4; ++mt)
                ldm_x4(afr[mt], sa + ((aRowSel + mt * 16) * KPAD + k0 + aColSel) * 2);
            #pragma unroll
            for (int nt = 0; nt < 4; ++nt)
                ldm_x2(bfr[nt], sb + ((bRowSel + nt * 8) * KPAD + k0 + bColSel) * 2);
            #pragma unroll
            for (int mt = 0; mt < 4; ++mt)
                #pragma unroll
                for (int nt = 0; nt < 4; ++nt)
                    mma_bf16(acc[mt][nt], afr[mt], bfr[nt]);
        }
        __syncthreads();
        if (it + GSTAGES < KITERS) { ISSUE_STAGE(it + GSTAGES, s); cp_commit(); }
    }

    const int er = lane >> 2;
    const int ec = (lane & 3) * 2;
    #pragma unroll
    for (int mt = 0; mt < 4; ++mt) {
        #pragma unroll
        for (int nt = 0; nt < 4; ++nt) {
            const int r  = m0 + wm + mt * 16 + er;
            const int cc = n0 + wn + nt * 8 + ec;
            *(float2*)(C + (size_t)r * N + cc)       = make_float2(acc[mt][nt][0], acc[mt][nt][1]);
            *(float2*)(C + (size_t)(r + 8) * N + cc) = make_float2(acc[mt][nt][2], acc[mt][nt][3]);
        }
    }
    #undef ISSUE_STAGE
}

// ---------------------------------------------------------------------------
// fp32 -> bf16 3-term split (verbatim R3 — VERIFIED)
// ---------------------------------------------------------------------------
__global__ void conv_split_A(const float* __restrict__ src, __nv_bfloat16* __restrict__ dst, int K)
{
    long t = (long)blockIdx.x * blockDim.x + threadIdx.x;
    long total = (long)BT * K;
    if (t >= total) return;
    long m = t / K, k = t - m * K;
    float a = src[t];
    __nv_bfloat16 hi = __float2bfloat16(a);
    __nv_bfloat16 lo = __float2bfloat16(a - __bfloat162float(hi));
    long base = m * (3L * K) + k;
    dst[base]         = hi;
    dst[base + K]     = hi;
    dst[base + 2 * K] = lo;
}

__global__ void conv_split_W(const float* __restrict__ W, __nv_bfloat16* __restrict__ Bt,
                             int K, int N)
{
    __shared__ float tile[32][33];
    const int k0 = blockIdx.y * 32, n0 = blockIdx.x * 32;
    for (int i = threadIdx.y; i < 32; i += 8)
        tile[i][threadIdx.x] = W[(long)(k0 + i) * N + n0 + threadIdx.x];
    __syncthreads();
    for (int i = threadIdx.y; i < 32; i += 8) {
        int n = n0 + i, k = k0 + threadIdx.x;
        float a = tile[threadIdx.x][i];
        __nv_bfloat16 hi = __float2bfloat16(a);
        __nv_bfloat16 lo = __float2bfloat16(a - __bfloat162float(hi));
        long base = (long)n * (3L * K) + k;
        Bt[base]         = hi;
        Bt[base + K]     = lo;
        Bt[base + 2 * K] = hi;
    }
}

// ---------------------------------------------------------------------------
// Flash attention — R3-verified numerics, restructured for occupancy:
// 2 threads per query (each owns 32 of 64 dims). 256 threads = 128 queries.
// Score = partial dot + shfl_xor(1); softmax state duplicated per pair
// (bit-identical in both lanes). Mask/early-exit identical to R3.
// ---------------------------------------------------------------------------
#define QT 128
#define KT 64
#define KC 8

__global__ __launch_bounds__(256)
void attn2(const float* __restrict__ qkv, const int* __restrict__ pos,
           float* __restrict__ out)
{
    __shared__ float Ks[KT][HDim];
    __shared__ float Vs[KT][HDim];
    __shared__ int   pk[KT];

    const int t    = threadIdx.x;
    const int qloc = t >> 1;          // 0..127
    const int half = t & 1;           // dim half
    const int qt   = blockIdx.x;
    const int h    = blockIdx.y;
    const int b    = blockIdx.z;

    const int qi = qt * QT + qloc;
    const long rowQ = (long)(b * Tv + qi) * QKVN + h * HDim + half * 32;

    float q[32];
    #pragma unroll
    for (int d = 0; d < 32; d += 4) {
        float4 v = *(const float4*)(qkv + rowQ + d);
        q[d] = v.x; q[d+1] = v.y; q[d+2] = v.z; q[d+3] = v.w;
    }
    const int pq     = pos[b * Tv + qi];
    const int p_last = pos[b * Tv + qt * QT + QT - 1];

    float o[32];
    #pragma unroll
    for (int d = 0; d < 32; ++d) o[d] = 0.f;
    float m = -1e30f, l = 0.f;
    const float scale = 0.125f;

    // K/V tile load mapping: 256 threads x 16 floats = 4096 = 64x64
    const int lr  = t >> 2;           // 0..63 (row)
    const int lc0 = (t & 3) * 16;     // col base

    for (int k0 = 0; k0 < Tv; k0 += KT) {
        __syncthreads();
        if (t < KT) pk[t] = pos[b * Tv + k0 + t];
        {
            const long rowK = (long)(b * Tv + k0 + lr) * QKVN + Dv + h * HDim + lc0;
            const long rowV = rowK + Dv;
            #pragma unroll
            for (int cc = 0; cc < 16; cc += 4) {
                *(float4*)(&Ks[lr][lc0 + cc]) = *(const float4*)(qkv + rowK + cc);
                *(float4*)(&Vs[lr][lc0 + cc]) = *(const float4*)(qkv + rowV + cc);
            }
        }
        __syncthreads();
        if (pk[0] > p_last) break;   // uniform across block

        #pragma unroll 1
        for (int j0 = 0; j0 < KT; j0 += KC) {
            float s[KC];
            float tmax = -1e30f;
            #pragma unroll
            for (int j = 0; j < KC; ++j) {
                float a0 = 0.f, a1 = 0.f, a2 = 0.f, a3 = 0.f;
                const float4* kr = (const float4*)(&Ks[j0 + j][half * 32]);
                #pragma unroll
                for (int d4 = 0; d4 < 8; ++d4) {
                    float4 kv = kr[d4];
                    a0 = fmaf(q[d4*4+0], kv.x, a0);
                    a1 = fmaf(q[d4*4+1], kv.y, a1);
                    a2 = fmaf(q[d4*4+2], kv.z, a2);
                    a3 = fmaf(q[d4*4+3], kv.w, a3);
                }
                float part = (a0 + a1) + (a2 + a3);
                float full = part + __shfl_xor_sync(0xffffffffu, part, 1);
                float sc = full * scale;
                if (pk[j0 + j] > pq) sc = -1e30f;
                s[j] = sc;
                tmax = fmaxf(tmax, sc);
            }
            if (tmax > -1e29f) {
                const float mn   = fmaxf(m, tmax);
                const float corr = __expf(m - mn);
                m = mn;
                float ls = 0.f;
                #pragma unroll
                for (int j = 0; j < KC; ++j) {
                    float p = __expf(s[j] - mn);
                    s[j] = p;
                    ls += p;
                }
                l = l * corr + ls;
                #pragma unroll
                for (int d = 0; d < 32; ++d) o[d] *= corr;
                #pragma unroll
                for (int j = 0; j < KC; ++j) {
                    const float p = s[j];
                    const float4* vr = (const float4*)(&Vs[j0 + j][half * 32]);
                    #pragma unroll
                    for (int d4 = 0; d4 < 8; ++d4) {
                        float4 vv = vr[d4];
                        o[d4*4+0] = fmaf(p, vv.x, o[d4*4+0]);
                        o[d4*4+1] = fmaf(p, vv.y, o[d4*4+1]);
                        o[d4*4+2] = fmaf(p, vv.z, o[d4*4+2]);
                        o[d4*4+3] = fmaf(p, vv.w, o[d4*4+3]);
                    }
                }
            }
        }
    }

    const float inv_l = 1.f / l;
    float* orow = out + (long)(b * Tv + qi) * Dv + h * HDim + half * 32;
    #pragma unroll
    for (int d = 0; d < 32; d += 4) {
        float4 v = make_float4(o[d] * inv_l, o[d+1] * inv_l,
                               o[d+2] * inv_l, o[d+3] * inv_l);
        *(float4*)(orow + d) = v;
    }
}

// ---------------------------------------------------------------------------
// Launch
// ---------------------------------------------------------------------------
extern "C" void kernel_launch(void* const* d_in, const int* in_sizes, int n_in,
                              void* d_out, int out_size)
{
    const float* x    = (const float*)d_in[0];
    const int*   pos  = (const int*)d_in[1];
    const float* Wqkv = (const float*)d_in[2];
    const float* Wout = (const float*)d_in[3];
    float*       outp = (float*)d_out;

    float *qkv_p, *attn_p;
    __nv_bfloat16 *A1_p, *A2_p, *Bt1_p, *Bt2_p;
    cudaGetSymbolAddress((void**)&qkv_p,  g_qkv);
    cudaGetSymbolAddress((void**)&attn_p, g_attn);
    cudaGetSymbolAddress((void**)&A1_p,   g_A1);
    cudaGetSymbolAddress((void**)&A2_p,   g_A2);
    cudaGetSymbolAddress((void**)&Bt1_p,  g_Bt1);
    cudaGetSymbolAddress((void**)&Bt2_p,  g_Bt2);

    cudaFuncSetAttribute(gemm_mma, cudaFuncAttributeMaxDynamicSharedMemorySize, GEMM_SMEM);

    // 1) Split-convert x & Wqkv (bf16 3-term, verified)
    {
        long total = (long)BT * Dv;
        conv_split_A<<<(unsigned)((total + 255) / 256), 256>>>(x, A1_p, Dv);
        dim3 gw(QKVN / 32, Dv / 32);
        conv_split_W<<<gw, dim3(32, 8)>>>(Wqkv, Bt1_p, Dv, QKVN);
    }
    // 2) QKV projection
    {
        dim3 grid(QKVN / BN, BT / BM);
        gemm_mma<<<grid, 256, GEMM_SMEM>>>(A1_p, Bt1_p, qkv_p, QKVN);
    }
    // 3) Attention (2 threads per query)
    {
        dim3 grid(Tv / QT, NH, Bv);
        attn2<<<grid, 256>>>(qkv_p, pos, attn_p);
    }
    // 4) Output projection
    {
        long total = (long)BT * Dv;
        conv_split_A<<<(unsigned)((total + 255) / 256), 256>>>(attn_p, A2_p, Dv);
        dim3 gw(Dv / 32, Dv / 32);
        conv_split_W<<<gw, dim3(32, 8)>>>(Wout, Bt2_p, Dv, Dv);
        dim3 grid(Dv / BN, BT / BM);
        gemm_mma<<<grid, 256, GEMM_SMEM>>>(A2_p, Bt2_p, outp, Dv);
    }
}

// round 12
// speedup vs baseline: 1.3819x; 1.3819x over previous
#include <cuda_runtime.h>
#include <cuda_fp16.h>
#include <cstdint>

// Problem constants
#define Bv   4
#define Tv   2048
#define Dv   1024
#define NH   16
#define HDim 64
#define BT   (Bv * Tv)          // 8192
#define QKVN (3 * Dv)           // 3072
#define KEFF 2048               // fp16 split-K: A=[hi|lo], B=[hi|hi]

// ---------------------------------------------------------------------------
// Scratch (device globals; no allocation allowed)
// ---------------------------------------------------------------------------
__device__ float  g_qkv[BT * QKVN];              // fp32 qkv          96MB
__device__ __half g_A1[(size_t)BT * KEFF];       // x split           32MB
__device__ __half g_A2[(size_t)BT * KEFF];       // attn-out split    32MB
__device__ __half g_Bt1[(size_t)QKVN * KEFF];    // Wqkv^T hi|hi      12MB
__device__ __half g_Bt2[(size_t)Dv * KEFF];      // Wout^T hi|hi       4MB

// ---------------------------------------------------------------------------
// Helpers
// ---------------------------------------------------------------------------
__device__ __forceinline__ uint32_t smem_u32(const void* p) {
    uint32_t a;
    asm("{ .reg .u64 t; cvta.to.shared.u64 t, %1; cvt.u32.u64 %0, t; }" : "=r"(a) : "l"(p));
    return a;
}
__device__ __forceinline__ void cp_async16(uint32_t dst, const void* src) {
    asm volatile("cp.async.cg.shared.global [%0], [%1], 16;" :: "r"(dst), "l"(src));
}
__device__ __forceinline__ void cp_commit() {
    asm volatile("cp.async.commit_group;" ::: "memory");
}
template <int N>
__device__ __forceinline__ void cp_wait() {
    asm volatile("cp.async.wait_group %0;" :: "n"(N) : "memory");
}
__device__ __forceinline__ void ldm_x4(uint32_t* r, uint32_t addr) {
    asm volatile("ldmatrix.sync.aligned.m8n8.x4.shared.b16 {%0,%1,%2,%3}, [%4];"
                 : "=r"(r[0]), "=r"(r[1]), "=r"(r[2]), "=r"(r[3]) : "r"(addr));
}
__device__ __forceinline__ void ldm_x2(uint32_t* r, uint32_t addr) {
    asm volatile("ldmatrix.sync.aligned.m8n8.x2.shared.b16 {%0,%1}, [%2];"
                 : "=r"(r[0]), "=r"(r[1]) : "r"(addr));
}
__device__ __forceinline__ void mma_f16(float* d, const uint32_t* a, const uint32_t* b) {
    asm volatile(
        "mma.sync.aligned.m16n8k16.row.col.f32.f16.f16.f32 "
        "{%0,%1,%2,%3}, {%4,%5,%6,%7}, {%8,%9}, {%0,%1,%2,%3};"
        : "+f"(d[0]), "+f"(d[1]), "+f"(d[2]), "+f"(d[3])
        : "r"(a[0]), "r"(a[1]), "r"(a[2]), "r"(a[3]), "r"(b[0]), "r"(b[1]));
}

// ---------------------------------------------------------------------------
// fp16 HMMA GEMM — identical structure to R3-verified kernel; dtype=fp16,
// KEFF=2048. C[M,N] = A[M,KEFF] @ Bt[N,KEFF]^T (both K-contiguous)
// ---------------------------------------------------------------------------
#define BM 128
#define BN 128
#define BK 32
#define KPAD 40
#define GSTAGES 3
#define KITERS (KEFF / BK)      // 64
#define STAGE_ELEMS ((BM + BN) * KPAD)
#define GEMM_SMEM (GSTAGES * STAGE_ELEMS * 2)

__global__ void __launch_bounds__(256)
gemm_mma(const __half* __restrict__ A, const __half* __restrict__ Bt,
         float* __restrict__ C, int N)
{
    extern __shared__ __half smg[];
    const int tid  = threadIdx.x;
    const int lane = tid & 31;
    const int wid  = tid >> 5;
    const int wm   = (wid & 1) * 64;
    const int wn   = (wid >> 1) * 32;
    const int m0   = blockIdx.y * BM;
    const int n0   = blockIdx.x * BN;

    const uint32_t smb = smem_u32(smg);

    const int idxA0 = tid * 2;
    const int rowA0 = idxA0 >> 2, kcA0 = (idxA0 & 3) * 8;
    const int rowA1 = (idxA0 + 1) >> 2, kcA1 = ((idxA0 + 1) & 3) * 8;

    float acc[4][4][4] = {};

    #define ISSUE_STAGE(it, s) do { \
        const __half* ga = A  + (size_t)m0 * KEFF + (it) * BK; \
        const __half* gb = Bt + (size_t)n0 * KEFF + (it) * BK; \
        uint32_t sa = smb + (uint32_t)(s) * STAGE_ELEMS * 2; \
        uint32_t sb = sa + BM * KPAD * 2; \
        cp_async16(sa + (rowA0 * KPAD + kcA0) * 2, ga + (size_t)rowA0 * KEFF + kcA0); \
        cp_async16(sa + (rowA1 * KPAD + kcA1) * 2, ga + (size_t)rowA1 * KEFF + kcA1); \
        cp_async16(sb + (rowA0 * KPAD + kcA0) * 2, gb + (size_t)rowA0 * KEFF + kcA0); \
        cp_async16(sb + (rowA1 * KPAD + kcA1) * 2, gb + (size_t)rowA1 * KEFF + kcA1); \
    } while (0)

    #pragma unroll
    for (int s = 0; s < GSTAGES; ++s) { ISSUE_STAGE(s, s); cp_commit(); }

    const int aRowSel = wm + (lane & 15);
    const int aColSel = (lane >> 4) << 3;
    const int bRowSel = wn + (lane & 7);
    const int bColSel = ((lane >> 3) & 1) << 3;

    for (int it = 0; it < KITERS; ++it) {
        const int s = it % GSTAGES;
        cp_wait<GSTAGES - 1>();
        __syncthreads();

        const uint32_t sa = smb + (uint32_t)s * STAGE_ELEMS * 2;
        const uint32_t sb = sa + BM * KPAD * 2;

        #pragma unroll
        for (int ks = 0; ks < 2; ++ks) {
            const int k0 = ks * 16;
            uint32_t afr[4][4], bfr[4][2];
            #pragma unroll
            for (int mt = 0; mt < 4; ++mt)
                ldm_x4(afr[mt], sa + ((aRowSel + mt * 16) * KPAD + k0 + aColSel) * 2);
            #pragma unroll
            for (int nt = 0; nt < 4; ++nt)
                ldm_x2(bfr[nt], sb + ((bRowSel + nt * 8) * KPAD + k0 + bColSel) * 2);
            #pragma unroll
            for (int mt = 0; mt < 4; ++mt)
                #pragma unroll
                for (int nt = 0; nt < 4; ++nt)
                    mma_f16(acc[mt][nt], afr[mt], bfr[nt]);
        }
        __syncthreads();
        if (it + GSTAGES < KITERS) { ISSUE_STAGE(it + GSTAGES, s); cp_commit(); }
    }

    const int er = lane >> 2;
    const int ec = (lane & 3) * 2;
    #pragma unroll
    for (int mt = 0; mt < 4; ++mt) {
        #pragma unroll
        for (int nt = 0; nt < 4; ++nt) {
            const int r  = m0 + wm + mt * 16 + er;
            const int cc = n0 + wn + nt * 8 + ec;
            *(float2*)(C + (size_t)r * N + cc)       = make_float2(acc[mt][nt][0], acc[mt][nt][1]);
            *(float2*)(C + (size_t)(r + 8) * N + cc) = make_float2(acc[mt][nt][2], acc[mt][nt][3]);
        }
    }
    #undef ISSUE_STAGE
}

// ---------------------------------------------------------------------------
// fp32 -> fp16 2-term splits. A: [hi|lo] along K. W^T: [hi|hi].
// ---------------------------------------------------------------------------
__global__ void conv_split_A(const float* __restrict__ src, __half* __restrict__ dst, int K)
{
    long t = (long)blockIdx.x * blockDim.x + threadIdx.x;
    long total = (long)BT * K;
    if (t >= total) return;
    long m = t / K, k = t - m * K;
    float a = src[t];
    __half hi = __float2half(a);
    __half lo = __float2half(a - __half2float(hi));
    long base = m * (2L * K) + k;
    dst[base]     = hi;
    dst[base + K] = lo;
}

__global__ void conv_split_W(const float* __restrict__ W, __half* __restrict__ Bt,
                             int K, int N)
{
    __shared__ float tile[32][33];
    const int k0 = blockIdx.y * 32, n0 = blockIdx.x * 32;
    for (int i = threadIdx.y; i < 32; i += 8)
        tile[i][threadIdx.x] = W[(long)(k0 + i) * N + n0 + threadIdx.x];
    __syncthreads();
    for (int i = threadIdx.y; i < 32; i += 8) {
        int n = n0 + i, k = k0 + threadIdx.x;
        __half hi = __float2half(tile[threadIdx.x][i]);
        long base = (long)n * (2L * K) + k;
        Bt[base]     = hi;
        Bt[base + K] = hi;
    }
}

// ---------------------------------------------------------------------------
// Flash attention — VERBATIM R3-verified numerics (1 thread/query, 128 q/CTA,
// 64-key SMEM tiles, 16-key register chunks, prefix mask + block early exit).
// Only change: output written directly as fp16 [hi|lo] split rows for the
// output-projection GEMM (eliminates the fp32 attn buffer + conversion pass).
// ---------------------------------------------------------------------------
#define QT 128
#define KT 64
#define KC 16

__global__ __launch_bounds__(128)
void attn_kernel(const float* __restrict__ qkv, const int* __restrict__ pos,
                 __half* __restrict__ outA)
{
    __shared__ float Ks[KT][HDim];
    __shared__ float Vs[KT][HDim];
    __shared__ int   pk[KT];

    const int t  = threadIdx.x;
    const int qt = blockIdx.x;
    const int h  = blockIdx.y;
    const int b  = blockIdx.z;

    const int qi = qt * QT + t;
    const long rowQ = (long)(b * Tv + qi) * QKVN + h * HDim;

    float q[HDim];
    #pragma unroll
    for (int d = 0; d < HDim; d += 4) {
        float4 v = *(const float4*)(qkv + rowQ + d);
        q[d] = v.x; q[d+1] = v.y; q[d+2] = v.z; q[d+3] = v.w;
    }
    const int pq     = pos[b * Tv + qi];
    const int p_last = pos[b * Tv + qt * QT + QT - 1];

    float o[HDim];
    #pragma unroll
    for (int d = 0; d < HDim; ++d) o[d] = 0.f;
    float m = -1e30f, l = 0.f;
    const float scale = 0.125f;

    for (int k0 = 0; k0 < Tv; k0 += KT) {
        __syncthreads();
        if (t < KT) pk[t] = pos[b * Tv + k0 + t];
        {
            const int r  = t >> 1;
            const int c0 = (t & 1) * 32;
            const long rowK = (long)(b * Tv + k0 + r) * QKVN + Dv + h * HDim + c0;
            const long rowV = rowK + Dv;
            #pragma unroll
            for (int cc = 0; cc < 32; cc += 4) {
                *(float4*)(&Ks[r][c0 + cc]) = *(const float4*)(qkv + rowK + cc);
                *(float4*)(&Vs[r][c0 + cc]) = *(const float4*)(qkv + rowV + cc);
            }
        }
        __syncthreads();
        if (pk[0] > p_last) break;

        #pragma unroll 1
        for (int j0 = 0; j0 < KT; j0 += KC) {
            float s[KC];
            float tmax = -1e30f;
            #pragma unroll
            for (int j = 0; j < KC; ++j) {
                float a0 = 0.f, a1 = 0.f, a2 = 0.f, a3 = 0.f;
                const float4* kr = (const float4*)(&Ks[j0 + j][0]);
                #pragma unroll
                for (int d4 = 0; d4 < HDim / 4; ++d4) {
                    float4 kv = kr[d4];
                    a0 = fmaf(q[d4*4+0], kv.x, a0);
                    a1 = fmaf(q[d4*4+1], kv.y, a1);
                    a2 = fmaf(q[d4*4+2], kv.z, a2);
                    a3 = fmaf(q[d4*4+3], kv.w, a3);
                }
                float sc = ((a0 + a1) + (a2 + a3)) * scale;
                if (pk[j0 + j] > pq) sc = -1e30f;
                s[j] = sc;
                tmax = fmaxf(tmax, sc);
            }
            if (tmax > -1e29f) {
                const float mn   = fmaxf(m, tmax);
                const float corr = __expf(m - mn);
                m = mn;
                float ls = 0.f;
                #pragma unroll
                for (int j = 0; j < KC; ++j) {
                    float p = __expf(s[j] - mn);
                    s[j] = p;
                    ls += p;
                }
                l = l * corr + ls;
                #pragma unroll
                for (int d = 0; d < HDim; ++d) o[d] *= corr;
                #pragma unroll
                for (int j = 0; j < KC; ++j) {
                    const float p = s[j];
                    const float4* vr = (const float4*)(&Vs[j0 + j][0]);
                    #pragma unroll
                    for (int d4 = 0; d4 < HDim / 4; ++d4) {
                        float4 vv = vr[d4];
                        o[d4*4+0] = fmaf(p, vv.x, o[d4*4+0]);
                        o[d4*4+1] = fmaf(p, vv.y, o[d4*4+1]);
                        o[d4*4+2] = fmaf(p, vv.z, o[d4*4+2]);
                        o[d4*4+3] = fmaf(p, vv.w, o[d4*4+3]);
                    }
                }
            }
        }
    }

    // Direct fp16 hi/lo split store: row layout [hi(0..1023) | lo(0..1023)]
    const float inv_l = 1.f / l;
    __half* arow = outA + (size_t)(b * Tv + qi) * (2 * Dv) + h * HDim;
    #pragma unroll
    for (int d = 0; d < HDim; ++d) {
        float v = o[d] * inv_l;
        __half hi = __float2half(v);
        __half lo = __float2half(v - __half2float(hi));
        arow[d]      = hi;
        arow[Dv + d] = lo;
    }
}

// ---------------------------------------------------------------------------
// Launch
// ---------------------------------------------------------------------------
extern "C" void kernel_launch(void* const* d_in, const int* in_sizes, int n_in,
                              void* d_out, int out_size)
{
    const float* x    = (const float*)d_in[0];
    const int*   pos  = (const int*)d_in[1];
    const float* Wqkv = (const float*)d_in[2];
    const float* Wout = (const float*)d_in[3];
    float*       outp = (float*)d_out;

    float* qkv_p;
    __half *A1_p, *A2_p, *Bt1_p, *Bt2_p;
    cudaGetSymbolAddress((void**)&qkv_p,  g_qkv);
    cudaGetSymbolAddress((void**)&A1_p,   g_A1);
    cudaGetSymbolAddress((void**)&A2_p,   g_A2);
    cudaGetSymbolAddress((void**)&Bt1_p,  g_Bt1);
    cudaGetSymbolAddress((void**)&Bt2_p,  g_Bt2);

    cudaFuncSetAttribute(gemm_mma, cudaFuncAttributeMaxDynamicSharedMemorySize, GEMM_SMEM);

    // 1) Split-convert x & Wqkv (fp16 2-term)
    {
        long total = (long)BT * Dv;
        conv_split_A<<<(unsigned)((total + 255) / 256), 256>>>(x, A1_p, Dv);
        dim3 gw(QKVN / 32, Dv / 32);
        conv_split_W<<<gw, dim3(32, 8)>>>(Wqkv, Bt1_p, Dv, QKVN);
    }
    // 2) QKV projection (fp16 HMMA, KEFF=2048)
    {
        dim3 grid(QKVN / BN, BT / BM);
        gemm_mma<<<grid, 256, GEMM_SMEM>>>(A1_p, Bt1_p, qkv_p, QKVN);
    }
    // 3) Attention (R3-verified SIMT; writes fp16 split directly)
    {
        dim3 grid(Tv / QT, NH, Bv);
        attn_kernel<<<grid, 128>>>(qkv_p, pos, A2_p);
    }
    // 4) Output projection (fp16 HMMA)
    {
        dim3 gw(Dv / 32, Dv / 32);
        conv_split_W<<<gw, dim3(32, 8)>>>(Wout, Bt2_p, Dv, Dv);
        dim3 grid(Dv / BN, BT / BM);
        gemm_mma<<<grid, 256, GEMM_SMEM>>>(A2_p, Bt2_p, outp, Dv);
    }
}